// round 14
// baseline (speedup 1.0000x reference)
#include <cuda_runtime.h>
#include <math_constants.h>
#include <cstdint>

#define TRAJ        128
#define NNODES      1048576
#define NGRAPH      8192

__device__ float4 g_scratch[2 * NNODES];   // node i: [2i]={p.xyz, cum_dist}, [2i+1]={dr_.xyz, cum_msd}
__device__ float2 g_aux[NNODES];           // {cum_dist, cum_msd} compact copy for X-compose
__device__ float  g_cm[NNODES];            // local (within-graph) cummax of dr_norm
__device__ float  g_graphMax[NGRAPH];
__device__ float  g_fv[NGRAPH];            // dr_norm at first node of graph

// ---------------------------------------------------------------------------
// Kernel A: per-graph features. 1 block (128 thr) per graph.  (R8 version)
// ---------------------------------------------------------------------------
__global__ void __launch_bounds__(128) kernelA(
    const float* __restrict__ P,
    float4* __restrict__ scr,
    float2* __restrict__ aux,
    float*  __restrict__ cmOut,
    float*  __restrict__ S,
    float*  __restrict__ U,
    float*  __restrict__ gMax,
    float*  __restrict__ gFv)
{
    const int g = blockIdx.x;
    const int t = threadIdx.x;
    const int lane = t & 31;
    const int w = t >> 5;

    __shared__ float4 sP4[96];
    float* sP = (float*)sP4;
    __shared__ float red[4][4];
    __shared__ float wsum[4], wsum2[4], wmax[4];

    const float4* Pg = (const float4*)(P + (size_t)g * (TRAJ * 3));
    if (t < 96) sP4[t] = Pg[t];
    __syncthreads();

    float px = sP[3*t], py = sP[3*t+1], pz = sP[3*t+2];
    float dx = 0.f, dy = 0.f, dz = 0.f;
    if (t < TRAJ - 1) {
        dx = sP[3*t+3] - px;
        dy = sP[3*t+4] - py;
        dz = sP[3*t+5] - pz;
    }

    // 4-value block reduction: sum P (3) + sum |P|^2 (1)
    float v[4] = { px, py, pz, px*px + py*py + pz*pz };
    #pragma unroll
    for (int k = 0; k < 4; k++) {
        #pragma unroll
        for (int off = 16; off; off >>= 1)
            v[k] += __shfl_xor_sync(0xffffffffu, v[k], off);
    }
    if (lane == 0) {
        #pragma unroll
        for (int k = 0; k < 4; k++) red[w][k] = v[k];
    }
    __syncthreads();
    float tot[4];
    #pragma unroll
    for (int k = 0; k < 4; k++)
        tot[k] = red[0][k] + red[1][k] + red[2][k] + red[3][k];

    const float invL = 1.0f / (float)TRAJ;
    float mx = tot[0]*invL, my = tot[1]*invL, mz = tot[2]*invL;
    float var = tot[3]*invL - (mx*mx + my*my + mz*mz);
    float pstd = sqrtf(var);
    float isf = 1.0f / pstd;

    float pnx = px*isf, pny = py*isf, pnz = pz*isf;
    float rdx = dx*isf, rdy = dy*isf, rdz = dz*isf;
    float dn  = sqrtf(1e-5f + rdx*rdx + rdy*rdy + rdz*rdz);
    float dn2 = dn * dn;

    float cs = dn, cs2 = dn2, cm = dn;
    #pragma unroll
    for (int off = 1; off < 32; off <<= 1) {
        float a  = __shfl_up_sync(0xffffffffu, cs,  off);
        float a2 = __shfl_up_sync(0xffffffffu, cs2, off);
        float am = __shfl_up_sync(0xffffffffu, cm,  off);
        if (lane >= off) { cs += a; cs2 += a2; cm = fmaxf(cm, am); }
    }
    if (lane == 31) { wsum[w] = cs; wsum2[w] = cs2; wmax[w] = cm; }
    __syncthreads();
    float o = 0.f, o2 = 0.f, om = -CUDART_INF_F;
    for (int j = 0; j < w; j++) { o += wsum[j]; o2 += wsum2[j]; om = fmaxf(om, wmax[j]); }
    cs += o; cs2 += o2; cm = fmaxf(cm, om);

    const int i = g * TRAJ + t;
    scr[2*i]     = make_float4(pnx, pny, pnz, cs);
    scr[2*i + 1] = make_float4(rdx, rdy, rdz, cs2);
    aux[i]   = make_float2(cs, cs2);
    cmOut[i] = cm;

    if (t == TRAJ - 1) gMax[g] = cm;
    if (t == 0) {
        gFv[g] = dn;
        S[2*g]     = pstd;
        S[2*g + 1] = (float)TRAJ;
        // telescoped mean jump: sum dr = P[last] - P[first]  (fill_last => exact)
        float ux = (sP[381] - sP[0]) * invL;
        float uy = (sP[382] - sP[1]) * invL;
        float uz = (sP[383] - sP[2]) * invL;
        float ui = 1.0f / sqrtf(1e-5f + ux*ux + uy*uy + uz*uz);
        U[3*g]     = ux * ui;
        U[3*g + 1] = uy * ui;
        U[3*g + 2] = uz * ui;
    }
}

// ---------------------------------------------------------------------------
// Fused kernel D+C. D blocks first: 1024 edges per block (8 passes/warp),
// ONE smem buffer + ONE 20480B TMA store -> half the barriers/TMA issues
// per edge vs 512-edge blocks. Trailing C blocks compose X, each computing
// its own global-max prefix from the L2-hot gMax array.
// ---------------------------------------------------------------------------
__global__ void __launch_bounds__(256, 8) kernelDC(
    const int* __restrict__ row,
    const int* __restrict__ col,
    const float4* __restrict__ scr,
    float* __restrict__ Eo,
    int Ecount, int dblk,
    const float2* __restrict__ aux,
    const float*  __restrict__ cmIn,
    const float*  __restrict__ gMax,
    const float*  __restrict__ gFv,
    float* __restrict__ X)
{
    const int t = threadIdx.x;

    if (blockIdx.x >= (unsigned)dblk) {
        // ---- C part: compose X (256 nodes = 2 graphs per block) ----
        const int b  = blockIdx.x - dblk;
        const int g0 = 2 * b;                       // first graph of this block
        const int lane = t & 31;
        const int w = t >> 5;
        __shared__ float s_wm[8];
        __shared__ float s_gp[2];

        // block-reduce max over gMax[0 .. g0-1]
        float m = -CUDART_INF_F;
        for (int j = t; j < g0; j += 256) m = fmaxf(m, gMax[j]);
        #pragma unroll
        for (int off = 16; off; off >>= 1)
            m = fmaxf(m, __shfl_xor_sync(0xffffffffu, m, off));
        if (lane == 0) s_wm[w] = m;
        __syncthreads();
        if (t == 0) {
            float M = s_wm[0];
            #pragma unroll
            for (int j = 1; j < 8; j++) M = fmaxf(M, s_wm[j]);
            s_gp[0] = M;                            // gpfx for graph g0
            s_gp[1] = fmaxf(M, gMax[g0]);           // gpfx for graph g0+1
        }
        __syncthreads();

        const int i = b * 256 + t;
        const int half = t >> 7;                    // which of the 2 graphs
        float cm  = cmIn[i];
        float gp  = s_gp[half];
        float fv  = __ldg(gFv + g0 + half);
        float2 ab = __ldg(aux + i);
        float4 xo = make_float4((float)((i & (TRAJ-1)) + 1) * (1.0f / (float)TRAJ),
                                ab.x, ab.y, fmaxf(cm, gp) + fv);
        __stcs(((float4*)X) + i, xo);
        return;
    }

    // ---- D part: edge features (1024 edges/block, 128 per warp) ----
    __shared__ __align__(16) float sm[1024 * 5];
    const int warp = t >> 5;
    const int lane = t & 31;
    const int k = lane >> 1;             // pair index 0..15
    const int h = lane & 1;              // half selector
    const int base = blockIdx.x * 1024;
    const bool full = (base + 1024 <= Ecount);

    if (full) {
        #pragma unroll
        for (int pass = 0; pass < 8; pass++) {
            const int eb = warp * 128 + pass * 16 + k;
            const int e  = base + eb;
            const int r = __ldcs(row + e);
            const int c = __ldcs(col + e);
            // lanes 2k,2k+1 hit adjacent float4s of one endpoint's 128B line
            // in the same instruction -> one wavefront per endpoint.
            float4 Ar = __ldg(scr + 2*r + h);
            float4 Ac = __ldg(scr + 2*c + h);
            float fa, fb = Ar.w - Ac.w;   // h=0: d_cum_dist, h=1: d_cum_msd
            if (h == 0) {
                float ddx = Ar.x - Ac.x, ddy = Ar.y - Ac.y, ddz = Ar.z - Ac.z;
                fa = sqrtf(ddx*ddx + ddy*ddy + ddz*ddz);          // d
                sm[eb*5 + 0] = (float)((r & (TRAJ-1)) - (c & (TRAJ-1))) * (1.0f / (float)TRAJ);
                sm[eb*5 + 1] = fa;
                sm[eb*5 + 3] = fb;
            } else {
                fa = Ar.x*Ac.x + Ar.y*Ac.y + Ar.z*Ac.z;           // corr
                sm[eb*5 + 2] = fa;
                sm[eb*5 + 4] = fb;
            }
        }
        __syncthreads();

        if (t == 0) {
            // order generic-proxy STS before async-proxy TMA read of smem
            asm volatile("fence.proxy.async.shared::cta;" ::: "memory");
            unsigned int s_sm = (unsigned int)__cvta_generic_to_shared(sm);
            asm volatile(
                "cp.async.bulk.global.shared::cta.bulk_group [%0], [%1], %2;"
                :: "l"(Eo + (size_t)base * 5), "r"(s_sm), "r"(20480u)
                : "memory");
            asm volatile("cp.async.bulk.commit_group;" ::: "memory");
            asm volatile("cp.async.bulk.wait_group 0;" ::: "memory");
        }
    } else {
        // tail fallback (not hit for E = 8,388,608, kept for generality)
        #pragma unroll
        for (int pass = 0; pass < 8; pass++) {
            const int eb = warp * 128 + pass * 16 + k;
            const int e  = base + eb;
            float fa = 0.f, fb = 0.f, f0 = 0.f;
            if (e < Ecount) {
                const int r = __ldcs(row + e);
                const int c = __ldcs(col + e);
                float4 Ar = __ldg(scr + 2*r + h);
                float4 Ac = __ldg(scr + 2*c + h);
                if (h == 0) {
                    float ddx = Ar.x - Ac.x, ddy = Ar.y - Ac.y, ddz = Ar.z - Ac.z;
                    fa = sqrtf(ddx*ddx + ddy*ddy + ddz*ddz);
                } else {
                    fa = Ar.x*Ac.x + Ar.y*Ac.y + Ar.z*Ac.z;
                }
                fb = Ar.w - Ac.w;
                f0 = (float)((r & (TRAJ-1)) - (c & (TRAJ-1))) * (1.0f / (float)TRAJ);
            }
            if (h == 0) {
                sm[eb*5 + 0] = f0;
                sm[eb*5 + 1] = fa;
                sm[eb*5 + 3] = fb;
            } else {
                sm[eb*5 + 2] = fa;
                sm[eb*5 + 4] = fb;
            }
        }
        __syncthreads();
        const int nvalid = Ecount - base;
        if (nvalid > 0) {
            const int nf = nvalid * 5;
            for (int j = t; j < nf; j += 256) __stcs(Eo + (size_t)base * 5 + j, sm[j]);
        }
    }
}

// ---------------------------------------------------------------------------
extern "C" void kernel_launch(void* const* d_in, const int* in_sizes, int n_in,
                              void* d_out, int out_size)
{
    const float* P   = (const float*)d_in[0];
    const int*   row = (const int*)d_in[2];
    const int*   col = (const int*)d_in[3];

    const int N = in_sizes[0] / 3;
    const int G = N / TRAJ;
    const int E = in_sizes[2];

    float* out = (float*)d_out;
    float* X  = out;                       // [N,4]
    float* Eo = out + (size_t)4 * N;       // [E,5]
    float* S  = Eo + (size_t)5 * E;        // [G,2]
    float* U  = S + (size_t)2 * G;         // [G,3]

    float4* scr;  cudaGetSymbolAddress((void**)&scr,  g_scratch);
    float2* aux;  cudaGetSymbolAddress((void**)&aux,  g_aux);
    float*  cm;   cudaGetSymbolAddress((void**)&cm,   g_cm);
    float*  gMax; cudaGetSymbolAddress((void**)&gMax, g_graphMax);
    float*  gFv;  cudaGetSymbolAddress((void**)&gFv,  g_fv);

    const int dblk = (E + 1023) / 1024;
    const int cblk = N / 256;

    kernelA<<<G, 128>>>(P, scr, aux, cm, S, U, gMax, gFv);
    kernelDC<<<dblk + cblk, 256>>>(row, col, scr, Eo, E, dblk,
                                   aux, cm, gMax, gFv, X);
}

// round 16
// speedup vs baseline: 1.1312x; 1.1312x over previous
#include <cuda_runtime.h>
#include <math_constants.h>
#include <cstdint>

#define TRAJ        128
#define NNODES      1048576
#define NGRAPH      8192

__device__ float4 g_scratch[2 * NNODES];   // node i: [2i]={p.xyz, cum_dist}, [2i+1]={dr_.xyz, cum_msd}
__device__ float  g_cm[NNODES];            // local (within-graph) cummax of dr_norm
__device__ float  g_graphMax[NGRAPH];
__device__ float  g_fv[NGRAPH];            // dr_norm at first node of graph

// ---------------------------------------------------------------------------
// Kernel A: per-graph features. 1 block (128 thr) per graph.
// ---------------------------------------------------------------------------
__global__ void __launch_bounds__(128) kernelA(
    const float* __restrict__ P,
    float4* __restrict__ scr,
    float*  __restrict__ cmOut,
    float*  __restrict__ S,
    float*  __restrict__ U,
    float*  __restrict__ gMax,
    float*  __restrict__ gFv)
{
    const int g = blockIdx.x;
    const int t = threadIdx.x;
    const int lane = t & 31;
    const int w = t >> 5;

    __shared__ float4 sP4[96];
    float* sP = (float*)sP4;
    __shared__ float red[4][4];
    __shared__ float wsum[4], wsum2[4], wmax[4];

    const float4* Pg = (const float4*)(P + (size_t)g * (TRAJ * 3));
    if (t < 96) sP4[t] = Pg[t];
    __syncthreads();

    float px = sP[3*t], py = sP[3*t+1], pz = sP[3*t+2];
    float dx = 0.f, dy = 0.f, dz = 0.f;
    if (t < TRAJ - 1) {
        dx = sP[3*t+3] - px;
        dy = sP[3*t+4] - py;
        dz = sP[3*t+5] - pz;
    }

    // 4-value block reduction: sum P (3) + sum |P|^2 (1)
    float v[4] = { px, py, pz, px*px + py*py + pz*pz };
    #pragma unroll
    for (int k = 0; k < 4; k++) {
        #pragma unroll
        for (int off = 16; off; off >>= 1)
            v[k] += __shfl_xor_sync(0xffffffffu, v[k], off);
    }
    if (lane == 0) {
        #pragma unroll
        for (int k = 0; k < 4; k++) red[w][k] = v[k];
    }
    __syncthreads();
    float tot[4];
    #pragma unroll
    for (int k = 0; k < 4; k++)
        tot[k] = red[0][k] + red[1][k] + red[2][k] + red[3][k];

    const float invL = 1.0f / (float)TRAJ;
    float mx = tot[0]*invL, my = tot[1]*invL, mz = tot[2]*invL;
    float var = tot[3]*invL - (mx*mx + my*my + mz*mz);
    float pstd = sqrtf(var);
    float isf = 1.0f / pstd;

    float pnx = px*isf, pny = py*isf, pnz = pz*isf;
    float rdx = dx*isf, rdy = dy*isf, rdz = dz*isf;
    float dn  = sqrtf(1e-5f + rdx*rdx + rdy*rdy + rdz*rdz);
    float dn2 = dn * dn;

    float cs = dn, cs2 = dn2, cm = dn;
    #pragma unroll
    for (int off = 1; off < 32; off <<= 1) {
        float a  = __shfl_up_sync(0xffffffffu, cs,  off);
        float a2 = __shfl_up_sync(0xffffffffu, cs2, off);
        float am = __shfl_up_sync(0xffffffffu, cm,  off);
        if (lane >= off) { cs += a; cs2 += a2; cm = fmaxf(cm, am); }
    }
    if (lane == 31) { wsum[w] = cs; wsum2[w] = cs2; wmax[w] = cm; }
    __syncthreads();
    float o = 0.f, o2 = 0.f, om = -CUDART_INF_F;
    for (int j = 0; j < w; j++) { o += wsum[j]; o2 += wsum2[j]; om = fmaxf(om, wmax[j]); }
    cs += o; cs2 += o2; cm = fmaxf(cm, om);

    const int i = g * TRAJ + t;
    scr[2*i]     = make_float4(pnx, pny, pnz, cs);
    scr[2*i + 1] = make_float4(rdx, rdy, rdz, cs2);
    cmOut[i] = cm;

    if (t == TRAJ - 1) gMax[g] = cm;
    if (t == 0) {
        gFv[g] = dn;
        S[2*g]     = pstd;
        S[2*g + 1] = (float)TRAJ;
        // telescoped mean jump: sum dr = P[last] - P[first]  (fill_last => exact)
        float ux = (sP[381] - sP[0]) * invL;
        float uy = (sP[382] - sP[1]) * invL;
        float uz = (sP[383] - sP[2]) * invL;
        float ui = 1.0f / sqrtf(1e-5f + ux*ux + uy*uy + uz*uz);
        U[3*g]     = ux * ui;
        U[3*g + 1] = uy * ui;
        U[3*g + 2] = uz * ui;
    }
}

// ---------------------------------------------------------------------------
// Fused kernel D+C. D blocks first (512-edge tile, R13 shape). Per-thread
// edges are CONTIGUOUS (4k..4k+3) so row/col load as one int4 each.
// Trailing C blocks compose X, each computing its own global-max prefix
// from the L2-hot gMax array; they read scr.w directly (no aux copy).
// ---------------------------------------------------------------------------
__global__ void __launch_bounds__(256, 4) kernelDC(
    const int* __restrict__ row,
    const int* __restrict__ col,
    const float4* __restrict__ scr,
    float* __restrict__ Eo,
    int Ecount, int dblk,
    const float*  __restrict__ cmIn,
    const float*  __restrict__ gMax,
    const float*  __restrict__ gFv,
    float* __restrict__ X)
{
    const int t = threadIdx.x;

    if (blockIdx.x >= (unsigned)dblk) {
        // ---- C part: compose X (256 nodes = 2 graphs per block) ----
        const int b  = blockIdx.x - dblk;
        const int g0 = 2 * b;                       // first graph of this block
        const int lane = t & 31;
        const int w = t >> 5;
        __shared__ float s_wm[8];
        __shared__ float s_gp[2];

        // block-reduce max over gMax[0 .. g0-1]
        float m = -CUDART_INF_F;
        for (int j = t; j < g0; j += 256) m = fmaxf(m, gMax[j]);
        #pragma unroll
        for (int off = 16; off; off >>= 1)
            m = fmaxf(m, __shfl_xor_sync(0xffffffffu, m, off));
        if (lane == 0) s_wm[w] = m;
        __syncthreads();
        if (t == 0) {
            float M = s_wm[0];
            #pragma unroll
            for (int j = 1; j < 8; j++) M = fmaxf(M, s_wm[j]);
            s_gp[0] = M;                            // gpfx for graph g0
            s_gp[1] = fmaxf(M, gMax[g0]);           // gpfx for graph g0+1
        }
        __syncthreads();

        const int i = b * 256 + t;
        const int half = t >> 7;                    // which of the 2 graphs
        float cm  = cmIn[i];
        float gp  = s_gp[half];
        float fv  = __ldg(gFv + g0 + half);
        float cd  = __ldg(scr + 2*i).w;             // cum_dist (L2-hot)
        float cq  = __ldg(scr + 2*i + 1).w;         // cum_msd
        float4 xo = make_float4((float)((i & (TRAJ-1)) + 1) * (1.0f / (float)TRAJ),
                                cd, cq, fmaxf(cm, gp) + fv);
        __stcs(((float4*)X) + i, xo);
        return;
    }

    // ---- D part: edge features (512 edges/block, 64 per warp) ----
    __shared__ __align__(16) float sm[512 * 5];
    const int warp = t >> 5;
    const int lane = t & 31;
    const int k = lane >> 1;             // pair index 0..15
    const int h = lane & 1;              // half selector
    const int base = blockIdx.x * 512;
    const bool full = (base + 512 <= Ecount);

    if (full) {
        // one int4 per thread covers this thread's 4 contiguous edges
        const int e0 = base + warp * 64 + 4 * k;
        const int4 rr = __ldcs((const int4*)(row + e0));
        const int4 cc = __ldcs((const int4*)(col + e0));
        const int rA[4] = { rr.x, rr.y, rr.z, rr.w };
        const int cA[4] = { cc.x, cc.y, cc.z, cc.w };

        #pragma unroll
        for (int pass = 0; pass < 4; pass++) {
            const int eb = warp * 64 + 4 * k + pass; // edge idx within block
            const int r = rA[pass];
            const int c = cA[pass];
            // lanes 2k,2k+1 hit adjacent float4s of one endpoint's 128B line
            // in the same instruction -> one wavefront per endpoint.
            float4 Ar = __ldg(scr + 2*r + h);
            float4 Ac = __ldg(scr + 2*c + h);
            float fa, fb = Ar.w - Ac.w;   // h=0: d_cum_dist, h=1: d_cum_msd
            if (h == 0) {
                float ddx = Ar.x - Ac.x, ddy = Ar.y - Ac.y, ddz = Ar.z - Ac.z;
                fa = sqrtf(ddx*ddx + ddy*ddy + ddz*ddz);          // d
                sm[eb*5 + 0] = (float)((r & (TRAJ-1)) - (c & (TRAJ-1))) * (1.0f / (float)TRAJ);
                sm[eb*5 + 1] = fa;
                sm[eb*5 + 3] = fb;
            } else {
                fa = Ar.x*Ac.x + Ar.y*Ac.y + Ar.z*Ac.z;           // corr
                sm[eb*5 + 2] = fa;
                sm[eb*5 + 4] = fb;
            }
        }
        __syncthreads();

        if (t == 0) {
            // order generic-proxy STS before async-proxy TMA read of smem
            asm volatile("fence.proxy.async.shared::cta;" ::: "memory");
            unsigned int s_sm = (unsigned int)__cvta_generic_to_shared(sm);
            asm volatile(
                "cp.async.bulk.global.shared::cta.bulk_group [%0], [%1], %2;"
                :: "l"(Eo + (size_t)base * 5), "r"(s_sm), "r"(10240u)
                : "memory");
            asm volatile("cp.async.bulk.commit_group;" ::: "memory");
            asm volatile("cp.async.bulk.wait_group 0;" ::: "memory");
        }
    } else {
        // tail fallback (not hit for E = 8,388,608, kept for generality)
        #pragma unroll
        for (int pass = 0; pass < 4; pass++) {
            const int eb = warp * 64 + 4 * k + pass;
            const int e  = base + eb;
            float fa = 0.f, fb = 0.f, f0 = 0.f;
            if (e < Ecount) {
                const int r = __ldcs(row + e);
                const int c = __ldcs(col + e);
                float4 Ar = __ldg(scr + 2*r + h);
                float4 Ac = __ldg(scr + 2*c + h);
                if (h == 0) {
                    float ddx = Ar.x - Ac.x, ddy = Ar.y - Ac.y, ddz = Ar.z - Ac.z;
                    fa = sqrtf(ddx*ddx + ddy*ddy + ddz*ddz);
                } else {
                    fa = Ar.x*Ac.x + Ar.y*Ac.y + Ar.z*Ac.z;
                }
                fb = Ar.w - Ac.w;
                f0 = (float)((r & (TRAJ-1)) - (c & (TRAJ-1))) * (1.0f / (float)TRAJ);
            }
            if (h == 0) {
                sm[eb*5 + 0] = f0;
                sm[eb*5 + 1] = fa;
                sm[eb*5 + 3] = fb;
            } else {
                sm[eb*5 + 2] = fa;
                sm[eb*5 + 4] = fb;
            }
        }
        __syncthreads();
        const int nvalid = Ecount - base;
        if (nvalid > 0) {
            const int nf = nvalid * 5;
            for (int j = t; j < nf; j += 256) __stcs(Eo + (size_t)base * 5 + j, sm[j]);
        }
    }
}

// ---------------------------------------------------------------------------
extern "C" void kernel_launch(void* const* d_in, const int* in_sizes, int n_in,
                              void* d_out, int out_size)
{
    const float* P   = (const float*)d_in[0];
    const int*   row = (const int*)d_in[2];
    const int*   col = (const int*)d_in[3];

    const int N = in_sizes[0] / 3;
    const int G = N / TRAJ;
    const int E = in_sizes[2];

    float* out = (float*)d_out;
    float* X  = out;                       // [N,4]
    float* Eo = out + (size_t)4 * N;       // [E,5]
    float* S  = Eo + (size_t)5 * E;        // [G,2]
    float* U  = S + (size_t)2 * G;         // [G,3]

    float4* scr;  cudaGetSymbolAddress((void**)&scr,  g_scratch);
    float*  cm;   cudaGetSymbolAddress((void**)&cm,   g_cm);
    float*  gMax; cudaGetSymbolAddress((void**)&gMax, g_graphMax);
    float*  gFv;  cudaGetSymbolAddress((void**)&gFv,  g_fv);

    const int dblk = (E + 511) / 512;
    const int cblk = N / 256;

    kernelA<<<G, 128>>>(P, scr, cm, S, U, gMax, gFv);
    kernelDC<<<dblk + cblk, 256>>>(row, col, scr, Eo, E, dblk,
                                   cm, gMax, gFv, X);
}